// round 15
// baseline (speedup 1.0000x reference)
#include <cuda_runtime.h>
#include <cuda_fp16.h>

#define NN   50000
#define NE   800000
#define NG   64
#define DIN  128
#define HD   64
#define NH   4
#define FF   256   // HEADS*HID
#define NLAT 32
#define MT   3125  // NN/16 m-tiles (exact)

// ---- scratch (device globals; no allocation allowed) ----
__device__ float    g_h[NN * HD];          // layer output features
__device__ uint4    g_xlh[NN * FF / 8];    // fp16 source-side transform
__device__ uint4    g_xrh[NN * FF / 8];    // fp16 target-side transform
__device__ unsigned g_xa[MT * 8 * 32 * 4]; // X in mma A-fragment order (max K=128)
__device__ unsigned g_wl16[32 * 8 * 32 * 2]; // Wl in mma B-fragment order
__device__ unsigned g_wr16[32 * 8 * 32 * 2]; // Wr in mma B-fragment order
__device__ float    g_p[NE * NH];          // exp(logit) per edge/head
__device__ float    g_nsum[NN * NH];       // segment sum of p
__device__ float    g_agg[NN * HD];        // aggregation accumulator
__device__ float    g_pool[NG * HD];       // pooled per-graph features
__device__ int      g_src[NE];             // int32 edge sources
__device__ int      g_dst[NE];             // int32 edge destinations
__device__ int      g_batch[NN];           // int32 graph ids
__device__ int      g_is64;                // input index dtype flag

__device__ __forceinline__ unsigned packh2(float lo, float hi) {
    __half2 h = __floats2half2_rn(lo, hi);
    return *(unsigned*)&h;
}

// ---- detect whether edge_index buffer is int64 or int32 ----
__global__ void k_detect(const void* __restrict__ ei) {
    if (threadIdx.x == 0) {
        const unsigned long long* p = (const unsigned long long*)ei;
        int is64 = 1;
        for (int i = 0; i < 64; i++)
            if ((p[i] >> 32) != 0ull) { is64 = 0; break; }
        g_is64 = is64;
    }
}

// ---- convert indices to int32 once ----
__global__ void k_convert(const void* __restrict__ ei, const void* __restrict__ batch) {
    int i = blockIdx.x * 256 + threadIdx.x;
    int is64 = g_is64;
    if (i < NE) {
        if (is64) {
            g_src[i] = (int)((const long long*)ei)[i];
            g_dst[i] = (int)((const long long*)ei)[NE + i];
        } else {
            g_src[i] = ((const int*)ei)[i];
            g_dst[i] = ((const int*)ei)[NE + i];
        }
    }
    if (i < NN)
        g_batch[i] = is64 ? (int)((const long long*)batch)[i] : ((const int*)batch)[i];
}

// ---- fused per-layer prep: plane 0 = cvtX, plane 1 = cvtW (l+r), plane 2 = zero ----
// cvtX: frag uint idx = ((mt*Kt + ko)*32 + lane)*4 + r
//   row = mt*16 + (lane>>2) + (r&1)*8 ; k = ko*16 + (lane&3)*2 + (r>>1)*8
// cvtW: frag uint idx = ((nt*Kt + ko)*32 + lane)*2 + r
//   k = ko*16 + (lane&3)*2 + r*8 ; n = nt*8 + (lane>>2)
__global__ void k_prep(const float* __restrict__ X, const float* __restrict__ Wl,
                       const float* __restrict__ Wr, int K, int Kt) {
    int idx = blockIdx.x * 256 + threadIdx.x;
    if (blockIdx.y == 0) {                       // ---- cvtX ----
        int total = MT * Kt * 128;
        if (idx >= total) return;
        const float* Xp = X ? X : g_h;
        int r    = idx & 3;
        int lane = (idx >> 2) & 31;
        int q    = idx >> 7;
        int ko   = q % Kt;
        int mt   = q / Kt;
        int row = mt * 16 + (lane >> 2) + (r & 1) * 8;
        int k   = ko * 16 + (lane & 3) * 2 + (r >> 1) * 8;
        const float* p = Xp + (size_t)row * K + k;
        g_xa[idx] = packh2(p[0], p[1]);
    } else if (blockIdx.y == 1) {                // ---- cvtW (both) ----
        int total = 32 * Kt * 64;
        if (idx >= 2 * total) return;
        const float* W = (idx < total) ? Wl : Wr;
        unsigned* out  = (idx < total) ? g_wl16 : g_wr16;
        int i2 = (idx < total) ? idx : idx - total;
        int r    = i2 & 1;
        int lane = (i2 >> 1) & 31;
        int q    = i2 >> 6;
        int ko   = q % Kt;
        int nt   = q / Kt;
        int k = ko * 16 + (lane & 3) * 2 + r * 8;
        int n = nt * 8 + (lane >> 2);
        out[i2] = packh2(W[(size_t)k * FF + n], W[(size_t)(k + 1) * FF + n]);
    } else {                                     // ---- zero agg/nsum ----
        if (idx < NN * HD) g_agg[idx] = 0.f;
        if (idx < NN * NH) g_nsum[idx] = 0.f;
    }
}

// ---- HMMA m16n8k16 fp16->fp32 ----
__device__ __forceinline__ void mma16816(float* d, uint4 a, uint2 b) {
    asm("mma.sync.aligned.m16n8k16.row.col.f32.f16.f16.f32 "
        "{%0,%1,%2,%3}, {%4,%5,%6,%7}, {%8,%9}, {%0,%1,%2,%3};"
        : "+f"(d[0]), "+f"(d[1]), "+f"(d[2]), "+f"(d[3])
        : "r"(a.x), "r"(a.y), "r"(a.z), "r"(a.w), "r"(b.x), "r"(b.y));
}

// ---- tensor-core GEMM: out[NN x 256] fp16. 128 threads = 4 warps ----
__global__ void k_mma(int Kt) {
    int lane = threadIdx.x & 31;
    int nq   = threadIdx.x >> 5;       // 0..3
    int mt   = blockIdx.x;             // 0..MT-1
    const unsigned* wbuf = blockIdx.y ? g_wr16 : g_wl16;
    __half* out = (__half*)(blockIdx.y ? g_xrh : g_xlh);

    float d[8][4];
#pragma unroll
    for (int i = 0; i < 8; i++)
#pragma unroll
        for (int j = 0; j < 4; j++) d[i][j] = 0.f;

    for (int ko = 0; ko < Kt; ko++) {
        uint4 a = __ldg(&((const uint4*)g_xa)[(mt * Kt + ko) * 32 + lane]);
#pragma unroll
        for (int i = 0; i < 8; i++) {
            int nt = nq * 8 + i;
            uint2 b = __ldg(&((const uint2*)wbuf)[(nt * Kt + ko) * 32 + lane]);
            mma16816(d[i], a, b);
        }
    }

    int row = mt * 16 + (lane >> 2);
    int n0  = (lane & 3) * 2;
#pragma unroll
    for (int i = 0; i < 8; i++) {
        int n = (nq * 8 + i) * 8 + n0;
        *(__half2*)(out + (size_t)row * FF + n)       = __floats2half2_rn(d[i][0], d[i][1]);
        *(__half2*)(out + (size_t)(row + 8) * FF + n) = __floats2half2_rn(d[i][2], d[i][3]);
    }
}

// ---- per-edge logits -> exp -> segment sum (warp per edge, half2 math) ----
__global__ void k_logits(const float* __restrict__ att) {
    int e = (blockIdx.x * 256 + threadIdx.x) >> 5;
    int lane = threadIdx.x & 31;
    if (e >= NE) return;
    int src = g_src[e];
    int dst = g_dst[e];

    uint4 av = __ldg(&g_xlh[(size_t)src * 32 + lane]);
    uint4 bv = __ldg(&g_xrh[(size_t)dst * 32 + lane]);
    float4 w0 = __ldg((const float4*)(att + lane * 8));
    float4 w1 = __ldg((const float4*)(att + lane * 8 + 4));
    float wreg[8] = {w0.x, w0.y, w0.z, w0.w, w1.x, w1.y, w1.z, w1.w};

    const __half2* a2 = (const __half2*)&av;
    const __half2* b2 = (const __half2*)&bv;
    const __half2 c02 = __floats2half2_rn(0.2f, 0.2f);
    float acc = 0.f;
#pragma unroll
    for (int j = 0; j < 4; j++) {
        __half2 z  = __hadd2(a2[j], b2[j]);
        __half2 zl = __hmax2(z, __hmul2(z, c02));   // leaky_relu(z, 0.2)
        float2 f = __half22float2(zl);
        acc += f.x * wreg[2 * j] + f.y * wreg[2 * j + 1];
    }
    // reduce within each 8-lane group (one head per group: head = lane>>3)
    acc += __shfl_xor_sync(0xffffffffu, acc, 4);
    acc += __shfl_xor_sync(0xffffffffu, acc, 2);
    acc += __shfl_xor_sync(0xffffffffu, acc, 1);

    float h0 = __shfl_sync(0xffffffffu, acc, 0);
    float h1 = __shfl_sync(0xffffffffu, acc, 8);
    float h2 = __shfl_sync(0xffffffffu, acc, 16);
    float h3 = __shfl_sync(0xffffffffu, acc, 24);

    if (lane == 0) {
        // direct exp — logits are O(1..10); clamp at 80 keeps fp32 sums finite
        float p0 = expf(fminf(h0, 80.f));
        float p1 = expf(fminf(h1, 80.f));
        float p2 = expf(fminf(h2, 80.f));
        float p3 = expf(fminf(h3, 80.f));
        *(float4*)(g_p + (size_t)e * 4) = make_float4(p0, p1, p2, p3);
        atomicAdd((float4*)(g_nsum + (size_t)dst * 4),
                  make_float4(p0, p1, p2, p3));              // RED.128
    }
}

// ---- aggregation: 16 threads/edge, float4 RED; 0.25/denom folded here ----
__global__ void k_agg() {
    int tid = blockIdx.x * 256 + threadIdx.x;
    int e = tid >> 4;
    int q = tid & 15;
    if (e >= NE) return;
    int src = g_src[e];
    int dst = g_dst[e];
    float4 pv = *(const float4*)(g_p + (size_t)e * 4);
    float4 sv = __ldg((const float4*)(g_nsum + (size_t)dst * 4));
    float ah[4] = {pv.x * (0.25f / (sv.x + 1e-16f)),
                   pv.y * (0.25f / (sv.y + 1e-16f)),
                   pv.z * (0.25f / (sv.z + 1e-16f)),
                   pv.w * (0.25f / (sv.w + 1e-16f))};

    const __half* xl = (const __half*)&g_xlh[(size_t)src * 32];
    float4 acc = make_float4(0.f, 0.f, 0.f, 0.f);
#pragma unroll
    for (int h = 0; h < 4; h++) {
        uint2 raw = __ldg((const uint2*)(xl + h * 64 + q * 4));
        float2 f0 = __half22float2(*(const __half2*)&raw.x);
        float2 f1 = __half22float2(*(const __half2*)&raw.y);
        acc.x += ah[h] * f0.x;
        acc.y += ah[h] * f0.y;
        acc.z += ah[h] * f1.x;
        acc.w += ah[h] * f1.y;
    }
    atomicAdd((float4*)(g_agg + (size_t)dst * HD + q * 4), acc);   // RED.128
}

// ---- h = leaky_relu(agg + b, 0.1) ----
__global__ void k_epi(const float* __restrict__ b) {
    int i = blockIdx.x * 256 + threadIdx.x;
    if (i >= NN * HD) return;
    float v = g_agg[i] + b[i & 63];
    g_h[i] = fmaxf(v, 0.1f * v);
}

__global__ void k_poolzero() {
    int i = blockIdx.x * 256 + threadIdx.x;
    if (i < NG * HD) g_pool[i] = 0.f;
}

__global__ void k_pool() {
    int tid = blockIdx.x * 256 + threadIdx.x;
    int n = tid >> 4, q = tid & 15;
    if (n >= NN) return;
    int g = g_batch[n];
    float4 v = *(const float4*)(g_h + (size_t)n * HD + q * 4);
    atomicAdd((float4*)(g_pool + (size_t)g * HD + q * 4), v);
}

// ---- batchnorm over graphs + FC (single block) ----
__global__ void k_bnfc(const float* __restrict__ gamma, const float* __restrict__ beta,
                       const float* __restrict__ fcW, const float* __restrict__ fcb,
                       float* __restrict__ out) {
    __shared__ float sp[NG * HD];
    __shared__ float smean[HD], srstd[HD], sgam[HD], sbet[HD];
    int t = threadIdx.x;
    for (int i = t; i < NG * HD; i += 256) sp[i] = g_pool[i];
    __syncthreads();
    if (t < HD) {
        float m = 0.f;
        for (int g = 0; g < NG; g++) m += sp[g * HD + t];
        m *= (1.f / NG);
        float v = 0.f;
        for (int g = 0; g < NG; g++) { float dd = sp[g * HD + t] - m; v += dd * dd; }
        v *= (1.f / NG);
        smean[t] = m;
        srstd[t] = rsqrtf(v + 1e-5f);
        sgam[t] = gamma[t];
        sbet[t] = beta[t];
    }
    __syncthreads();
    for (int i = t; i < NG * HD; i += 256) {
        int d = i & (HD - 1);
        sp[i] = (sp[i] - smean[d]) * srstd[d] * sgam[d] + sbet[d];
    }
    __syncthreads();
    for (int o = t; o < NG * NLAT; o += 256) {
        int g = o >> 5, j = o & 31;
        float acc = fcb[j];
        for (int d = 0; d < HD; d++) acc += sp[g * HD + d] * fcW[j * HD + d];
        out[o] = acc;
    }
}

extern "C" void kernel_launch(void* const* d_in, const int* in_sizes, int n_in,
                              void* d_out, int out_size) {
    const float* x     = (const float*)d_in[0];
    const void*  ei    = d_in[1];
    const void*  batch = d_in[2];
    const float* Wl[3]  = {(const float*)d_in[3],  (const float*)d_in[7],  (const float*)d_in[11]};
    const float* Wr[3]  = {(const float*)d_in[4],  (const float*)d_in[8],  (const float*)d_in[12]};
    const float* att[3] = {(const float*)d_in[5],  (const float*)d_in[9],  (const float*)d_in[13]};
    const float* bia[3] = {(const float*)d_in[6],  (const float*)d_in[10], (const float*)d_in[14]};
    const float* gamma  = (const float*)d_in[15];
    const float* beta   = (const float*)d_in[16];
    const float* fcW    = (const float*)d_in[17];
    const float* fcb    = (const float*)d_in[18];
    float* out = (float*)d_out;

    const int TB = 256;
    int nInit = (NN * HD + TB - 1) / TB;
    int nLog  = (NE * 32 + TB - 1) / TB;
    int nAgg  = (NE * 16 + TB - 1) / TB;
    int nPool = (NN * 16 + TB - 1) / TB;
    int nPz   = (NG * HD + TB - 1) / TB;
    int nCvt  = (NE + TB - 1) / TB;

    k_detect <<<1, 32>>>(ei);
    k_convert<<<nCvt, TB>>>(ei, batch);

    for (int l = 0; l < 3; l++) {
        int K  = (l == 0) ? DIN : HD;
        int Kt = K >> 4;
        const float* Xp = (l == 0) ? x : nullptr;   // nullptr -> use g_h
        int nCvX = (MT * Kt * 128 + TB - 1) / TB;
        int nCvW = (2 * 32 * Kt * 64 + TB - 1) / TB;
        int nPrep = nCvX > nInit ? nCvX : nInit;
        if (nCvW > nPrep) nPrep = nCvW;

        k_prep  <<<dim3(nPrep, 3), TB>>>(Xp, Wl[l], Wr[l], K, Kt);
        k_mma   <<<dim3(MT, 2), 128>>>(Kt);
        k_logits<<<nLog, TB>>>(att[l]);
        k_agg   <<<nAgg, TB>>>();
        k_epi   <<<nInit, TB>>>(bia[l]);
    }
    k_poolzero<<<nPz, TB>>>();
    k_pool    <<<nPool, TB>>>();
    k_bnfc    <<<1, 256>>>(gamma, beta, fcW, fcb, out);
}

// round 16
// speedup vs baseline: 1.0256x; 1.0256x over previous
#include <cuda_runtime.h>
#include <cuda_fp16.h>

#define NN   50000
#define NE   800000
#define NG   64
#define DIN  128
#define HD   64
#define NH   4
#define FF   256   // HEADS*HID
#define NLAT 32
#define MT   3125  // NN/16 m-tiles (exact)

// ---- scratch (device globals; no allocation allowed) ----
__device__ float    g_h[NN * HD];          // layer output features
__device__ uint4    g_xlh[NN * FF / 8];    // fp16 source-side transform
__device__ uint4    g_xrh[NN * FF / 8];    // fp16 target-side transform
__device__ unsigned g_xa[MT * 8 * 32 * 4]; // X in mma A-fragment order (max K=128)
__device__ unsigned g_wl16[32 * 8 * 32 * 2]; // Wl in mma B-fragment order
__device__ unsigned g_wr16[32 * 8 * 32 * 2]; // Wr in mma B-fragment order
__device__ float    g_p[NE * NH];          // exp(logit) per edge/head
__device__ float    g_nsum[NN * NH];       // segment sum -> 0.25/denom
__device__ float    g_agg[NN * HD];        // aggregation accumulator
__device__ float    g_pool[NG * HD];       // pooled per-graph features
__device__ int      g_src[NE];             // int32 edge sources
__device__ int      g_dst[NE];             // int32 edge destinations
__device__ int      g_batch[NN];           // int32 graph ids
__device__ int      g_is64;                // input index dtype flag

__device__ __forceinline__ unsigned packh2(float lo, float hi) {
    __half2 h = __floats2half2_rn(lo, hi);
    return *(unsigned*)&h;
}

// ---- detect whether edge_index buffer is int64 or int32 ----
__global__ void k_detect(const void* __restrict__ ei) {
    if (threadIdx.x == 0) {
        const unsigned long long* p = (const unsigned long long*)ei;
        int is64 = 1;
        for (int i = 0; i < 64; i++)
            if ((p[i] >> 32) != 0ull) { is64 = 0; break; }
        g_is64 = is64;
    }
}

// ---- convert indices to int32 once ----
__global__ void k_convert(const void* __restrict__ ei, const void* __restrict__ batch) {
    int i = blockIdx.x * 256 + threadIdx.x;
    int is64 = g_is64;
    if (i < NE) {
        if (is64) {
            g_src[i] = (int)((const long long*)ei)[i];
            g_dst[i] = (int)((const long long*)ei)[NE + i];
        } else {
            g_src[i] = ((const int*)ei)[i];
            g_dst[i] = ((const int*)ei)[NE + i];
        }
    }
    if (i < NN)
        g_batch[i] = is64 ? (int)((const long long*)batch)[i] : ((const int*)batch)[i];
}

// ---- per-layer scratch init ----
__global__ void k_init() {
    int i = blockIdx.x * 256 + threadIdx.x;
    if (i < NN * HD) g_agg[i] = 0.f;
    if (i < NN * NH) g_nsum[i] = 0.f;
}

// ---- X (fp32 [NN x K]) -> g_xa in m16n8k16 A-fragment order ----
// frag uint idx = ((mt*Kt + ko)*32 + lane)*4 + r
// a_r: row = mt*16 + (lane>>2) + (r&1)*8 ; k = ko*16 + (lane&3)*2 + (r>>1)*8
__global__ void k_cvtX(const float* __restrict__ X, int K, int Kt) {
    int idx = blockIdx.x * 256 + threadIdx.x;
    int total = MT * Kt * 128;
    if (idx >= total) return;
    const float* Xp = X ? X : g_h;
    int r    = idx & 3;
    int lane = (idx >> 2) & 31;
    int q    = idx >> 7;           // mt*Kt + ko
    int ko   = q % Kt;
    int mt   = q / Kt;
    int row = mt * 16 + (lane >> 2) + (r & 1) * 8;
    int k   = ko * 16 + (lane & 3) * 2 + (r >> 1) * 8;
    const float* p = Xp + (size_t)row * K + k;
    g_xa[idx] = packh2(p[0], p[1]);
}

// ---- W (fp32 [K x 256]) -> B-fragment order; blockIdx.y selects Wl/Wr ----
__global__ void k_cvtW(const float* __restrict__ Wl, const float* __restrict__ Wr,
                       int K, int Kt) {
    int idx = blockIdx.x * 256 + threadIdx.x;
    int total = 32 * Kt * 64;
    if (idx >= total) return;
    const float* W = blockIdx.y ? Wr : Wl;
    unsigned* out  = blockIdx.y ? g_wr16 : g_wl16;
    int r    = idx & 1;
    int lane = (idx >> 1) & 31;
    int q    = idx >> 6;           // nt*Kt + ko
    int ko   = q % Kt;
    int nt   = q / Kt;
    int k = ko * 16 + (lane & 3) * 2 + r * 8;
    int n = nt * 8 + (lane >> 2);
    out[idx] = packh2(W[(size_t)k * FF + n], W[(size_t)(k + 1) * FF + n]);
}

// ---- HMMA m16n8k16 fp16->fp32 ----
__device__ __forceinline__ void mma16816(float* d, uint4 a, uint2 b) {
    asm("mma.sync.aligned.m16n8k16.row.col.f32.f16.f16.f32 "
        "{%0,%1,%2,%3}, {%4,%5,%6,%7}, {%8,%9}, {%0,%1,%2,%3};"
        : "+f"(d[0]), "+f"(d[1]), "+f"(d[2]), "+f"(d[3])
        : "r"(a.x), "r"(a.y), "r"(a.z), "r"(a.w), "r"(b.x), "r"(b.y));
}

// ---- tensor-core GEMM: 2 m-tiles per block (B-frag reuse, 2 indep MMA chains) ----
__global__ void __launch_bounds__(128) k_mma(int Kt) {
    int lane = threadIdx.x & 31;
    int nq   = threadIdx.x >> 5;       // 0..3
    int mt0  = blockIdx.x * 2;         // first of 2 m-tiles
    int two  = (mt0 + 1 < MT);
    const unsigned* wbuf = blockIdx.y ? g_wr16 : g_wl16;
    __half* out = (__half*)(blockIdx.y ? g_xrh : g_xlh);

    float d[2][8][4];
#pragma unroll
    for (int t = 0; t < 2; t++)
#pragma unroll
        for (int i = 0; i < 8; i++)
#pragma unroll
            for (int j = 0; j < 4; j++) d[t][i][j] = 0.f;

    int mt1 = two ? mt0 + 1 : mt0;
    for (int ko = 0; ko < Kt; ko++) {
        uint4 a0 = __ldg(&((const uint4*)g_xa)[(mt0 * Kt + ko) * 32 + lane]);
        uint4 a1 = __ldg(&((const uint4*)g_xa)[(mt1 * Kt + ko) * 32 + lane]);
#pragma unroll
        for (int i = 0; i < 8; i++) {
            int nt = nq * 8 + i;
            uint2 b = __ldg(&((const uint2*)wbuf)[(nt * Kt + ko) * 32 + lane]);
            mma16816(d[0][i], a0, b);
            mma16816(d[1][i], a1, b);
        }
    }

    int rbase = (lane >> 2);
    int n0    = (lane & 3) * 2;
#pragma unroll
    for (int t = 0; t < 2; t++) {
        if (t == 1 && !two) break;
        int row = (mt0 + t) * 16 + rbase;
#pragma unroll
        for (int i = 0; i < 8; i++) {
            int n = (nq * 8 + i) * 8 + n0;
            *(__half2*)(out + (size_t)row * FF + n)       = __floats2half2_rn(d[t][i][0], d[t][i][1]);
            *(__half2*)(out + (size_t)(row + 8) * FF + n) = __floats2half2_rn(d[t][i][2], d[t][i][3]);
        }
    }
}

// ---- per-edge logits -> exp -> segment sum (warp per edge, no max pass) ----
__global__ void k_logits(const float* __restrict__ att) {
    int e = (blockIdx.x * 256 + threadIdx.x) >> 5;
    int lane = threadIdx.x & 31;
    if (e >= NE) return;
    int src = g_src[e];
    int dst = g_dst[e];

    uint4 av = __ldg(&g_xlh[(size_t)src * 32 + lane]);
    uint4 bv = __ldg(&g_xrh[(size_t)dst * 32 + lane]);
    float4 w0 = __ldg((const float4*)(att + lane * 8));
    float4 w1 = __ldg((const float4*)(att + lane * 8 + 4));
    float wreg[8] = {w0.x, w0.y, w0.z, w0.w, w1.x, w1.y, w1.z, w1.w};

    const __half2* a2 = (const __half2*)&av;
    const __half2* b2 = (const __half2*)&bv;
    float acc = 0.f;
#pragma unroll
    for (int j = 0; j < 4; j++) {
        float2 fa = __half22float2(a2[j]);
        float2 fb = __half22float2(b2[j]);
        float z0 = fa.x + fb.x; z0 = fmaxf(z0, 0.2f * z0);
        float z1 = fa.y + fb.y; z1 = fmaxf(z1, 0.2f * z1);
        acc += z0 * wreg[2 * j] + z1 * wreg[2 * j + 1];
    }
    // reduce within each 8-lane group (one head per group: head = lane>>3)
    acc += __shfl_xor_sync(0xffffffffu, acc, 4);
    acc += __shfl_xor_sync(0xffffffffu, acc, 2);
    acc += __shfl_xor_sync(0xffffffffu, acc, 1);

    float h0 = __shfl_sync(0xffffffffu, acc, 0);
    float h1 = __shfl_sync(0xffffffffu, acc, 8);
    float h2 = __shfl_sync(0xffffffffu, acc, 16);
    float h3 = __shfl_sync(0xffffffffu, acc, 24);

    if (lane == 0) {
        // direct exp — logits are O(1..10); clamp at 80 keeps fp32 sums finite
        float p0 = expf(fminf(h0, 80.f));
        float p1 = expf(fminf(h1, 80.f));
        float p2 = expf(fminf(h2, 80.f));
        float p3 = expf(fminf(h3, 80.f));
        *(float4*)(g_p + (size_t)e * 4) = make_float4(p0, p1, p2, p3);
        atomicAdd((float4*)(g_nsum + (size_t)dst * 4),
                  make_float4(p0, p1, p2, p3));              // RED.128
    }
}

// ---- fold 0.25/denom into g_nsum once per node ----
__global__ void k_rcp() {
    int i = blockIdx.x * 256 + threadIdx.x;
    if (i < NN * NH) g_nsum[i] = 0.25f / (g_nsum[i] + 1e-16f);
}

// ---- aggregation: 16 threads/edge, float4 RED ----
__global__ void k_agg() {
    int tid = blockIdx.x * 256 + threadIdx.x;
    int e = tid >> 4;
    int q = tid & 15;
    if (e >= NE) return;
    int src = g_src[e];
    int dst = g_dst[e];
    float4 pv = *(const float4*)(g_p + (size_t)e * 4);
    float4 sv = __ldg((const float4*)(g_nsum + (size_t)dst * 4));
    float ah[4] = {pv.x * sv.x, pv.y * sv.y, pv.z * sv.z, pv.w * sv.w};

    const __half* xl = (const __half*)&g_xlh[(size_t)src * 32];
    float4 acc = make_float4(0.f, 0.f, 0.f, 0.f);
#pragma unroll
    for (int h = 0; h < 4; h++) {
        uint2 raw = __ldg((const uint2*)(xl + h * 64 + q * 4));
        float2 f0 = __half22float2(*(const __half2*)&raw.x);
        float2 f1 = __half22float2(*(const __half2*)&raw.y);
        acc.x += ah[h] * f0.x;
        acc.y += ah[h] * f0.y;
        acc.z += ah[h] * f1.x;
        acc.w += ah[h] * f1.y;
    }
    atomicAdd((float4*)(g_agg + (size_t)dst * HD + q * 4), acc);   // RED.128
}

// ---- h = leaky_relu(agg + b, 0.1); optionally zero pool buffer ----
__global__ void k_epi(const float* __restrict__ b, int zeropool) {
    int i = blockIdx.x * 256 + threadIdx.x;
    if (zeropool && i < NG * HD) g_pool[i] = 0.f;
    if (i >= NN * HD) return;
    float v = g_agg[i] + b[i & 63];
    g_h[i] = fmaxf(v, 0.1f * v);
}

__global__ void k_pool() {
    int tid = blockIdx.x * 256 + threadIdx.x;
    int n = tid >> 4, q = tid & 15;
    if (n >= NN) return;
    int g = g_batch[n];
    float4 v = *(const float4*)(g_h + (size_t)n * HD + q * 4);
    atomicAdd((float4*)(g_pool + (size_t)g * HD + q * 4), v);
}

// ---- batchnorm over graphs + FC (single block) ----
__global__ void k_bnfc(const float* __restrict__ gamma, const float* __restrict__ beta,
                       const float* __restrict__ fcW, const float* __restrict__ fcb,
                       float* __restrict__ out) {
    __shared__ float sp[NG * HD];
    __shared__ float smean[HD], srstd[HD], sgam[HD], sbet[HD];
    int t = threadIdx.x;
    for (int i = t; i < NG * HD; i += 256) sp[i] = g_pool[i];
    __syncthreads();
    if (t < HD) {
        float m = 0.f;
        for (int g = 0; g < NG; g++) m += sp[g * HD + t];
        m *= (1.f / NG);
        float v = 0.f;
        for (int g = 0; g < NG; g++) { float dd = sp[g * HD + t] - m; v += dd * dd; }
        v *= (1.f / NG);
        smean[t] = m;
        srstd[t] = rsqrtf(v + 1e-5f);
        sgam[t] = gamma[t];
        sbet[t] = beta[t];
    }
    __syncthreads();
    for (int i = t; i < NG * HD; i += 256) {
        int d = i & (HD - 1);
        sp[i] = (sp[i] - smean[d]) * srstd[d] * sgam[d] + sbet[d];
    }
    __syncthreads();
    for (int o = t; o < NG * NLAT; o += 256) {
        int g = o >> 5, j = o & 31;
        float acc = fcb[j];
        for (int d = 0; d < HD; d++) acc += sp[g * HD + d] * fcW[j * HD + d];
        out[o] = acc;
    }
}

extern "C" void kernel_launch(void* const* d_in, const int* in_sizes, int n_in,
                              void* d_out, int out_size) {
    const float* x     = (const float*)d_in[0];
    const void*  ei    = d_in[1];
    const void*  batch = d_in[2];
    const float* Wl[3]  = {(const float*)d_in[3],  (const float*)d_in[7],  (const float*)d_in[11]};
    const float* Wr[3]  = {(const float*)d_in[4],  (const float*)d_in[8],  (const float*)d_in[12]};
    const float* att[3] = {(const float*)d_in[5],  (const float*)d_in[9],  (const float*)d_in[13]};
    const float* bia[3] = {(const float*)d_in[6],  (const float*)d_in[10], (const float*)d_in[14]};
    const float* gamma  = (const float*)d_in[15];
    const float* beta   = (const float*)d_in[16];
    const float* fcW    = (const float*)d_in[17];
    const float* fcb    = (const float*)d_in[18];
    float* out = (float*)d_out;

    const int TB = 256;
    int nInit = (NN * HD + TB - 1) / TB;
    int nLog  = (NE * 32 + TB - 1) / TB;
    int nRcp  = (NN * NH + TB - 1) / TB;
    int nAgg  = (NE * 16 + TB - 1) / TB;
    int nPool = (NN * 16 + TB - 1) / TB;
    int nCvt  = (NE + TB - 1) / TB;
    int nMma  = (MT + 1) / 2;

    k_detect <<<1, 32>>>(ei);
    k_convert<<<nCvt, TB>>>(ei, batch);

    for (int l = 0; l < 3; l++) {
        int K  = (l == 0) ? DIN : HD;
        int Kt = K >> 4;
        const float* Xp = (l == 0) ? x : nullptr;   // nullptr -> use g_h
        int nCvX = (MT * Kt * 128 + TB - 1) / TB;
        int nCvW = (32 * Kt * 64 + TB - 1) / TB;

        k_init  <<<nInit, TB>>>();
        k_cvtX  <<<nCvX, TB>>>(Xp, K, Kt);
        k_cvtW  <<<dim3(nCvW, 2), TB>>>(Wl[l], Wr[l], K, Kt);
        k_mma   <<<dim3(nMma, 2), 128>>>(Kt);
        k_logits<<<nLog, TB>>>(att[l]);
        k_rcp   <<<nRcp, TB>>>();
        k_agg   <<<nAgg, TB>>>();
        k_epi   <<<nInit, TB>>>(bia[l], l == 0 ? 1 : 0);
    }
    k_pool    <<<nPool, TB>>>();
    k_bnfc    <<<1, 256>>>(gamma, beta, fcW, fcb, out);
}